// round 6
// baseline (speedup 1.0000x reference)
#include <cuda_runtime.h>
#include <math.h>
#include <limits.h>

#define Nn 30000
#define Ee 400000
#define C1n 15000
#define E2n 100000
#define C2n 7500
#define Bn 16

typedef unsigned long long ull;

// ---------------- zero-init block (single memset 0) ---------------------------
struct ZBlk {
    int   deg1[Nn], degD1[Nn];
    int   deg2[C1n], degD2[C1n], cntc1[C1n];
    float possum[C1n * 3];
    float gsum[Bn * 64];
    float gcnt[Bn];
    float maxabs;
};
// ---------------- 0xff-init block (single memset 0xff) ------------------------
struct FBlk {
    float xp[C1n * 32];      // bits 0xffffffff sentinel (loses to all atomicMaxFloat)
    float x3[C2n * 64];
    int   batchp[C1n];       // -1
    int   batch2[C2n];       // -1
};
__device__ ZBlk gz;
__device__ FBlk gf;

// ---------------- uninitialized scratch ----------------------------------------
__device__ int g_off1[Nn + 1], g_cur1[Nn], g_offD1[Nn + 1], g_curD1[Nn];
__device__ int g_off2[C1n + 1], g_cur2[C1n], g_offD2[C1n + 1], g_curD2[C1n];
__device__ int g_csr1[Ee], g_q1[Ee];
__device__ int g_q2[E2n], g_d2[E2n];
__device__ __align__(16) float g_buf1[(size_t)Ee * 32];
__device__ __align__(16) float g_buf2[(size_t)E2n * 64];   // ull pairs {m0,m1}
__device__ __align__(16) float g_G2[(size_t)C1n * 1600];   // pairs (c,c+32) at 2c,2c+1
__device__ __align__(16) float g_bb2[C1n * 64];

__device__ __forceinline__ void atomicMaxFloat(float* addr, float val) {
    if (val >= 0.f) atomicMax((int*)addr, __float_as_int(val));
    else            atomicMin((unsigned int*)addr, __float_as_uint(val));
}
__device__ __forceinline__ float elu1(float v) { return v > 0.f ? v : expm1f(v); }
__device__ __forceinline__ float fixneg(float v) { return (v > -3e38f) ? v : 0.f; } // NaN/sentinel -> 0

__device__ __forceinline__ ull fma2(ull a, ull b, ull c) {
    ull d;
    asm("fma.rn.f32x2 %0, %1, %2, %3;" : "=l"(d) : "l"(a), "l"(b), "l"(c));
    return d;
}
__device__ __forceinline__ ull pack2f(float a, float b) {
    ull r;
    asm("mov.b64 %0, {%1, %2};" : "=l"(r) : "f"(a), "f"(b));
    return r;
}
__device__ __forceinline__ ull dup2f(float a) {
    ull r;
    asm("mov.b64 %0, {%1, %1};" : "=l"(r) : "f"(a));
    return r;
}
__device__ __forceinline__ void unpack2f(float& a, float& b, ull v) {
    asm("mov.b64 {%0, %1}, %2;" : "=f"(a), "=f"(b) : "l"(v));
}

// ---------------- K1: degree histograms (1 edge / thread) ----------------------
__global__ void k_hist(const int* __restrict__ ei, const int* __restrict__ ei2,
                       const int* __restrict__ cl1) {
    int t = blockIdx.x * blockDim.x + threadIdx.x;
    if (t < Ee) {
        atomicAdd(&gz.deg1[ei[t]], 1);
        atomicAdd(&gz.degD1[ei[Ee + t]], 1);
    }
    if (t < E2n) {
        atomicAdd(&gz.deg2[ei2[t]], 1);
        atomicAdd(&gz.degD2[ei2[E2n + t]], 1);
    }
    if (t < Nn) atomicAdd(&gz.cntc1[cl1[t]], 1);
}

// ---------------- K2: exclusive scans (4 arrays, 1 block each) -----------------
__global__ void k_scan() {
    const int* deg; int* off; int* cur; int n;
    switch (blockIdx.x) {
        case 0:  deg = gz.deg1;  off = g_off1;  cur = g_cur1;  n = Nn;  break;
        case 1:  deg = gz.degD1; off = g_offD1; cur = g_curD1; n = Nn;  break;
        case 2:  deg = gz.deg2;  off = g_off2;  cur = g_cur2;  n = C1n; break;
        default: deg = gz.degD2; off = g_offD2; cur = g_curD2; n = C1n; break;
    }
    __shared__ int wsum[32];
    __shared__ int carry;
    int tid = threadIdx.x, lane = tid & 31, wid = tid >> 5;
    if (tid == 0) carry = 0;
    __syncthreads();
    for (int base = 0; base < n; base += 1024) {
        int idx = base + tid;
        int v = (idx < n) ? deg[idx] : 0;
        int incl = v;
#pragma unroll
        for (int o = 1; o < 32; o <<= 1) {
            int tt = __shfl_up_sync(0xffffffffu, incl, o);
            if (lane >= o) incl += tt;
        }
        if (lane == 31) wsum[wid] = incl;
        __syncthreads();
        if (wid == 0) {
            int s = wsum[lane];
#pragma unroll
            for (int o = 1; o < 32; o <<= 1) {
                int tt = __shfl_up_sync(0xffffffffu, s, o);
                if (lane >= o) s += tt;
            }
            wsum[lane] = s;
        }
        __syncthreads();
        int woff = (wid == 0) ? 0 : wsum[wid - 1];
        int c0 = carry;
        if (idx < n) { int ex = c0 + woff + incl - v; off[idx] = ex; cur[idx] = ex; }
        __syncthreads();
        if (tid == 0) carry = c0 + wsum[31];
        __syncthreads();
    }
    if (threadIdx.x == 0) off[n] = carry;
}

// ---------------- K3: scatter edge ids + dst slots + dst ids -------------------
__global__ void k_scat(const int* __restrict__ ei, const int* __restrict__ ei2) {
    int t = blockIdx.x * blockDim.x + threadIdx.x;
    if (t < Ee) {
        int q = atomicAdd(&g_curD1[ei[Ee + t]], 1);
        int p = atomicAdd(&g_cur1[ei[t]], 1);
        g_csr1[p] = t;
        g_q1[p] = q;
    }
    if (t < E2n) {
        int dst = ei2[E2n + t];
        int q = atomicAdd(&g_curD2[dst], 1);
        int p = atomicAdd(&g_cur2[ei2[t]], 1);
        g_q2[p] = q;
        g_d2[p] = dst;
    }
}

// ---------------- K4: conv1 by src — 2 edges per warp per shfl ------------------
// Lane l: output col pair (2c, 2c+1), c = l&15. Lanes 0-15 = edge A, 16-31 = edge B.
// h interleaved: lane 2r+b holds h_b[r]; one shfl with src = 2r+(lane>=16)
// broadcasts both edges' h_r in a single instruction.
__global__ void __launch_bounds__(256) k_conv1(
        const float* __restrict__ x, const float* __restrict__ ea,
        const float* __restrict__ w1a, const float* __restrict__ b1a,
        const float* __restrict__ w1b, const float* __restrict__ b1b) {
    __shared__ __align__(16) float w1s[4800 + 192];
    int tid = threadIdx.x;
    for (int j = tid; j < 1248; j += 256) {
        float4 val;
        if (j < 1200) val = ((const float4*)w1b)[j];
        else          val = ((const float4*)b1b)[j - 1200];
        ((float4*)w1s)[j] = val;
    }
    __syncthreads();
    int v = (blockIdx.x * blockDim.x + tid) >> 5;
    int lane = tid & 31;
    if (v >= Nn) return;
    int c2 = (lane & 15) * 2;       // my column pair
    int hiHalf = lane >> 4;          // 0 = edge A, 1 = edge B
    int rh1 = lane >> 1;             // h row for h1 (0..15)
    int rh2 = min(16 + rh1, 24);     // h row for h2 (16..24, clamped)
    int esel = lane & 1;             // which edge my h belongs to

    // per-lane edge-MLP weights for my two h rows
    float wl0 = w1a[rh1], wl1 = w1a[25 + rh1], wl2 = w1a[50 + rh1], bl = b1a[rh1];
    float wh0 = w1a[rh2], wh1 = w1a[25 + rh2], wh2 = w1a[50 + rh2], bh = b1a[rh2];

    float xv[6];
    ull xd[6];
#pragma unroll
    for (int i = 0; i < 6; i++) { xv[i] = x[v * 6 + i]; xd[i] = dup2f(xv[i]); }

    ull G2p[25];
#pragma unroll
    for (int r = 0; r < 25; r++) {
        ull a = 0ULL;
#pragma unroll
        for (int i = 0; i < 6; i++)
            a = fma2(xd[i], *(const ull*)&w1s[r * 192 + i * 32 + c2], a);
        G2p[r] = a;
    }
    ull bbp = 0ULL;
#pragma unroll
    for (int i = 0; i < 6; i++)
        bbp = fma2(xd[i], *(const ull*)&w1s[4800 + i * 32 + c2], bbp);

    int p0 = g_off1[v], p1 = g_off1[v + 1];
    for (int p = p0; p < p1; p += 2) {
        int pB = (p + 1 < p1) ? p + 1 : p;
        int eA = g_csr1[p], eB = g_csr1[pB];
        int pdA = g_q1[p], pdB = g_q1[pB];
        int e = esel ? eB : eA;
        float a0 = ea[3 * e], a1 = ea[3 * e + 1], a2 = ea[3 * e + 2];
        float h1 = fmaxf(fmaf(a0, wl0, fmaf(a1, wl1, fmaf(a2, wl2, bl))), 0.f);
        float h2 = fmaxf(fmaf(a0, wh0, fmaf(a1, wh1, fmaf(a2, wh2, bh))), 0.f);
        ull msgp = bbp;
#pragma unroll
        for (int r = 0; r < 16; r++) {
            float hr = __shfl_sync(0xffffffffu, h1, 2 * r + hiHalf);
            msgp = fma2(dup2f(hr), G2p[r], msgp);
        }
#pragma unroll
        for (int r = 16; r < 25; r++) {
            float hr = __shfl_sync(0xffffffffu, h2, 2 * (r - 16) + hiHalf);
            msgp = fma2(dup2f(hr), G2p[r], msgp);
        }
        int row = hiHalf ? pdB : pdA;
        *(ull*)&g_buf1[(size_t)row * 32 + c2] = msgp;
    }
}

// ---------------- K5: node1 = segment-mean(buf1) + root + elu + pool1 ----------
__global__ void k_node1(const float* __restrict__ x, const float* __restrict__ pos,
                        const int* __restrict__ batch, const int* __restrict__ cl1,
                        const float* __restrict__ root1, const float* __restrict__ bias1) {
    int n = (blockIdx.x * blockDim.x + threadIdx.x) >> 5;
    int lane = threadIdx.x & 31;
    if (n >= Nn) return;
    int p0 = g_offD1[n], p1 = g_offD1[n + 1];
    float acc = 0.f;
    for (int p = p0; p < p1; p++) acc += g_buf1[(size_t)p * 32 + lane];
    float v = acc / fmaxf((float)(p1 - p0), 1.f) + bias1[lane];
#pragma unroll
    for (int i = 0; i < 6; i++) v = fmaf(x[n * 6 + i], root1[i * 32 + lane], v);
    float x1 = elu1(v);
    int c = cl1[n];
    atomicMaxFloat(&gf.xp[c * 32 + lane], x1);
    if (lane < 3) atomicAdd(&gz.possum[c * 3 + lane], pos[n * 3 + lane]);
    if (lane == 0) atomicMax(&gf.batchp[c], batch[n]);
}

// ---------------- K6: global max |cart| (posp divided inline) ------------------
__global__ void k_maxabs(const int* __restrict__ ei2) {
    int e = blockIdx.x * blockDim.x + threadIdx.x;
    float m = 0.f;
    if (e < E2n) {
        int s = ei2[e], d = ei2[E2n + e];
        float is = 1.f / fmaxf((float)gz.cntc1[s], 1.f);
        float id = 1.f / fmaxf((float)gz.cntc1[d], 1.f);
#pragma unroll
        for (int k = 0; k < 3; k++)
            m = fmaxf(m, fabsf(gz.possum[s * 3 + k] * is - gz.possum[d * 3 + k] * id));
    }
#pragma unroll
    for (int o = 16; o; o >>= 1) m = fmaxf(m, __shfl_xor_sync(0xffffffffu, m, o));
    if ((threadIdx.x & 31) == 0) atomicMax((int*)&gz.maxabs, __float_as_int(m));
}

// ---------------- K7: G2 = xp @ w2b via packed f32x2 FMA -----------------------
__global__ void __launch_bounds__(256) k_G2(const float* __restrict__ w2b,
                                            const float* __restrict__ b2b) {
    __shared__ __align__(16) float wsp[2048];       // [i][c][2] pairs {w[c], w[c+32]}
    __shared__ __align__(16) float2 xdup[128 * 33]; // [vv][i] duplicated {x,x}
    int tid = threadIdx.x;
    int vbase = blockIdx.x * 128;
    int rs = blockIdx.y;
    const float* wsrc = (rs < 25) ? (w2b + rs * 2048) : b2b;
    for (int j = tid; j < 2048; j += 256) {
        int i = j >> 6, col = j & 63;
        int c = col & 31, s = col >> 5;
        wsp[i * 64 + c * 2 + s] = wsrc[j];
    }
    for (int idx = tid; idx < 4096; idx += 256) {
        int vv = idx >> 5, i = idx & 31;
        float val = (vbase + vv < C1n) ? fixneg(gf.xp[(vbase + vv) * 32 + i]) : 0.f;
        xdup[vv * 33 + i] = make_float2(val, val);
    }
    __syncthreads();
    int colg = tid & 7, nodeg = tid >> 3;
    int c4 = colg * 4;
    int n4 = nodeg * 4;
    ull acc[4][4];
#pragma unroll
    for (int n = 0; n < 4; n++)
#pragma unroll
        for (int p = 0; p < 4; p++) acc[n][p] = 0ULL;
#pragma unroll 8
    for (int i = 0; i < 32; i++) {
        ulonglong2 wA = *(const ulonglong2*)&wsp[i * 64 + c4 * 2];
        ulonglong2 wB = *(const ulonglong2*)&wsp[i * 64 + c4 * 2 + 4];
        ull xp_[4];
#pragma unroll
        for (int n = 0; n < 4; n++)
            xp_[n] = *(const ull*)&xdup[(n4 + n) * 33 + i];
#pragma unroll
        for (int n = 0; n < 4; n++) {
            acc[n][0] = fma2(wA.x, xp_[n], acc[n][0]);
            acc[n][1] = fma2(wA.y, xp_[n], acc[n][1]);
            acc[n][2] = fma2(wB.x, xp_[n], acc[n][2]);
            acc[n][3] = fma2(wB.y, xp_[n], acc[n][3]);
        }
    }
#pragma unroll
    for (int n = 0; n < 4; n++) {
        int v = vbase + n4 + n;
        if (v < C1n) {
            float* dst = (rs < 25) ? (g_G2 + (size_t)v * 1600 + rs * 64 + c4 * 2)
                                   : (g_bb2 + v * 64 + c4 * 2);
            ulonglong2 o0; o0.x = acc[n][0]; o0.y = acc[n][1];
            ulonglong2 o1; o1.x = acc[n][2]; o1.y = acc[n][3];
            *(ulonglong2*)dst = o0;
            *(ulonglong2*)(dst + 4) = o1;
        }
    }
}

// ---------------- K8: conv2 by src (warp per C1 node, no gathers) --------------
__global__ void k_conv2(const float* __restrict__ w2a, const float* __restrict__ b2a) {
    int v = (blockIdx.x * blockDim.x + threadIdx.x) >> 5;
    int lane = threadIdx.x & 31;
    if (v >= C1n) return;
    const ull* Gp = (const ull*)(g_G2 + (size_t)v * 1600);
    float G0[25], G1[25];
#pragma unroll
    for (int r = 0; r < 25; r++) {
        ull g = Gp[r * 32 + lane];
        unpack2f(G0[r], G1[r], g);
    }
    float bb0, bb1;
    {
        ull b = ((const ull*)g_bb2)[v * 32 + lane];
        unpack2f(bb0, bb1, b);
    }
    float invS = 1.f / fmaxf((float)gz.cntc1[v], 1.f);
    float pv0 = gz.possum[v * 3] * invS, pv1 = gz.possum[v * 3 + 1] * invS,
          pv2 = gz.possum[v * 3 + 2] * invS;
    float inv = 0.5f / gz.maxabs;
    float wa0 = 0.f, wa1 = 0.f, wa2 = 0.f, ba = 0.f;
    if (lane < 25) { wa0 = w2a[lane]; wa1 = w2a[25 + lane]; wa2 = w2a[50 + lane]; ba = b2a[lane]; }
    int p0 = g_off2[v], p1 = g_off2[v + 1];
    for (int p = p0; p < p1; p++) {
        int pd = g_q2[p];
        int dst = g_d2[p];
        float invD = 1.f / fmaxf((float)gz.cntc1[dst], 1.f);
        float e0 = fmaf(pv0 - gz.possum[dst * 3] * invD,     inv, 0.5f);
        float e1 = fmaf(pv1 - gz.possum[dst * 3 + 1] * invD, inv, 0.5f);
        float e2 = fmaf(pv2 - gz.possum[dst * 3 + 2] * invD, inv, 0.5f);
        float h = fmaxf(fmaf(e0, wa0, fmaf(e1, wa1, fmaf(e2, wa2, ba))), 0.f);
        float m0 = bb0, m1 = bb1;
#pragma unroll
        for (int r = 0; r < 25; r++) {
            float hr = __shfl_sync(0xffffffffu, h, r);
            m0 = fmaf(hr, G0[r], m0);
            m1 = fmaf(hr, G1[r], m1);
        }
        ((ull*)g_buf2)[(size_t)pd * 32 + lane] = pack2f(m0, m1);
    }
}

// ---------------- K9: node2 + pool2 scatter -------------------------------------
__global__ void k_node2(const int* __restrict__ cl2, const float* __restrict__ root2,
                        const float* __restrict__ bias2) {
    int c = (blockIdx.x * blockDim.x + threadIdx.x) >> 5;
    int lane = threadIdx.x & 31;
    if (c >= C1n) return;
    int p0 = g_offD2[c], p1 = g_offD2[c + 1];
    const ull ONE2 = pack2f(1.f, 1.f);
    ull accp = 0ULL;
    for (int p = p0; p < p1; p++)
        accp = fma2(((const ull*)g_buf2)[(size_t)p * 32 + lane], ONE2, accp);
    float a0, a1; unpack2f(a0, a1, accp);
    float cnt = fmaxf((float)(p1 - p0), 1.f);
    float v0 = a0 / cnt + bias2[lane];
    float v1 = a1 / cnt + bias2[lane + 32];
    float xpi = fixneg(gf.xp[c * 32 + lane]);
#pragma unroll 8
    for (int i = 0; i < 32; i++) {
        float xi = __shfl_sync(0xffffffffu, xpi, i);
        v0 = fmaf(xi, root2[i * 64 + lane], v0);
        v1 = fmaf(xi, root2[i * 64 + lane + 32], v1);
    }
    float e0 = elu1(v0), e1 = elu1(v1);
    int c2 = cl2[c];
    atomicMaxFloat(&gf.x3[c2 * 64 + lane], e0);
    atomicMaxFloat(&gf.x3[c2 * 64 + lane + 32], e1);
    if (lane == 0) atomicMax(&gf.batch2[c2], max(gf.batchp[c], 0));
}

// ---------------- K10: pool2 finalize + global mean scatter ---------------------
__global__ void k_pool2() {
    int c = (blockIdx.x * blockDim.x + threadIdx.x) >> 5;
    int lane = threadIdx.x & 31;
    if (c >= C2n) return;
    float v0 = fixneg(gf.x3[c * 64 + lane]);
    float v1 = fixneg(gf.x3[c * 64 + lane + 32]);
    int b = max(gf.batch2[c], 0);
    atomicAdd(&gz.gsum[b * 64 + lane], v0);
    atomicAdd(&gz.gsum[b * 64 + lane + 32], v1);
    if (lane == 0) atomicAdd(&gz.gcnt[b], 1.f);
}

// ---------------- K11: FC head + log_softmax ------------------------------------
__global__ void k_head(const float* __restrict__ fc1w, const float* __restrict__ fc1b,
                       const float* __restrict__ fc2w, const float* __restrict__ fc2b,
                       float* __restrict__ out) {
    __shared__ float g[16 * 64];
    __shared__ float hh[16 * 128];
    __shared__ float lg[16 * 10];
    int tid = threadIdx.x;
    for (int i = tid; i < 16 * 64; i += 256) g[i] = gz.gsum[i] / fmaxf(gz.gcnt[i >> 6], 1.f);
    __syncthreads();
    for (int o = tid; o < 16 * 128; o += 256) {
        int b = o >> 7, j = o & 127;
        float acc = fc1b[j];
        for (int k = 0; k < 64; k++) acc = fmaf(g[b * 64 + k], fc1w[k * 128 + j], acc);
        hh[o] = elu1(acc);
    }
    __syncthreads();
    if (tid < 160) {
        int b = tid / 10, k = tid % 10;
        float acc = fc2b[k];
        for (int j = 0; j < 128; j++) acc = fmaf(hh[b * 128 + j], fc2w[j * 10 + k], acc);
        lg[tid] = acc;
    }
    __syncthreads();
    if (tid < 16) {
        float m = -1e30f;
        for (int k = 0; k < 10; k++) m = fmaxf(m, lg[tid * 10 + k]);
        float s = 0.f;
        for (int k = 0; k < 10; k++) s += expf(lg[tid * 10 + k] - m);
        float ls = logf(s) + m;
        for (int k = 0; k < 10; k++) out[tid * 10 + k] = lg[tid * 10 + k] - ls;
    }
}

// ---------------- host launcher --------------------------------------------------
extern "C" void kernel_launch(void* const* d_in, const int* in_sizes, int n_in,
                              void* d_out, int out_size) {
    const float *x, *ea, *pos, *w1a, *b1a, *w1b, *b1b, *root1, *bias1;
    const float *w2a, *b2a, *w2b, *b2b, *root2, *bias2, *fc1w, *fc1b, *fc2w, *fc2b;
    const int *ei, *batch, *cl1, *ei2, *cl2;

    if (in_sizes[3] == 2 * Ee) {
        x = (const float*)d_in[0];  ea = (const float*)d_in[1];  pos = (const float*)d_in[2];
        ei = (const int*)d_in[3];   batch = (const int*)d_in[4]; cl1 = (const int*)d_in[5];
        ei2 = (const int*)d_in[6];  cl2 = (const int*)d_in[7];
        w1a = (const float*)d_in[8];  b1a = (const float*)d_in[9];
        w1b = (const float*)d_in[10]; b1b = (const float*)d_in[11];
        root1 = (const float*)d_in[12]; bias1 = (const float*)d_in[13];
        w2a = (const float*)d_in[14]; b2a = (const float*)d_in[15];
        w2b = (const float*)d_in[16]; b2b = (const float*)d_in[17];
        root2 = (const float*)d_in[18]; bias2 = (const float*)d_in[19];
        fc1w = (const float*)d_in[20]; fc1b = (const float*)d_in[21];
        fc2w = (const float*)d_in[22]; fc2b = (const float*)d_in[23];
    } else {
        x = (const float*)d_in[0];  ea = (const float*)d_in[1];  pos = (const float*)d_in[2];
        w1a = (const float*)d_in[3];  b1a = (const float*)d_in[4];
        w1b = (const float*)d_in[5];  b1b = (const float*)d_in[6];
        root1 = (const float*)d_in[7]; bias1 = (const float*)d_in[8];
        w2a = (const float*)d_in[9];  b2a = (const float*)d_in[10];
        w2b = (const float*)d_in[11]; b2b = (const float*)d_in[12];
        root2 = (const float*)d_in[13]; bias2 = (const float*)d_in[14];
        fc1w = (const float*)d_in[15]; fc1b = (const float*)d_in[16];
        fc2w = (const float*)d_in[17]; fc2b = (const float*)d_in[18];
        ei = (const int*)d_in[19];  batch = (const int*)d_in[20]; cl1 = (const int*)d_in[21];
        ei2 = (const int*)d_in[22]; cl2 = (const int*)d_in[23];
    }

    void *pz = nullptr, *pf = nullptr;
    cudaGetSymbolAddress(&pz, gz);
    cudaGetSymbolAddress(&pf, gf);
    cudaMemsetAsync(pz, 0, sizeof(ZBlk));
    cudaMemsetAsync(pf, 0xff, sizeof(FBlk));

    k_hist<<<(Ee + 255) / 256, 256>>>(ei, ei2, cl1);
    k_scan<<<4, 1024>>>();
    k_scat<<<(Ee + 255) / 256, 256>>>(ei, ei2);
    k_conv1<<<3750, 256>>>(x, ea, w1a, b1a, w1b, b1b);
    k_node1<<<3750, 256>>>(x, pos, batch, cl1, root1, bias1);
    k_maxabs<<<(E2n + 255) / 256, 256>>>(ei2);
    k_G2<<<dim3(118, 26), 256>>>(w2b, b2b);
    k_conv2<<<1875, 256>>>(w2a, b2a);
    k_node2<<<1875, 256>>>(cl2, root2, bias2);
    k_pool2<<<938, 256>>>();
    k_head<<<1, 256>>>(fc1w, fc1b, fc2w, fc2b, (float*)d_out);
}

// round 7
// speedup vs baseline: 1.0877x; 1.0877x over previous
#include <cuda_runtime.h>
#include <math.h>
#include <limits.h>

#define Nn 30000
#define Ee 400000
#define C1n 15000
#define E2n 100000
#define C2n 7500
#define Bn 16

typedef unsigned long long ull;

// ---------------- zero-init block (single memset 0) ---------------------------
struct ZBlk {
    int   deg1[Nn], degD1[Nn];
    int   deg2[C1n], degD2[C1n], cntc1[C1n];
    float possum[C1n * 3];
    float gsum[Bn * 64];
    float gcnt[Bn];
    float maxabs;
};
// ---------------- 0xff-init block (single memset 0xff) ------------------------
struct FBlk {
    float xp[C1n * 32];      // bits 0xffffffff sentinel (loses to all atomicMaxFloat)
    float x3[C2n * 64];
    int   batchp[C1n];       // -1
    int   batch2[C2n];       // -1
};
__device__ ZBlk gz;
__device__ FBlk gf;

// ---------------- uninitialized scratch ----------------------------------------
__device__ int g_off1[Nn + 1], g_cur1[Nn], g_offD1[Nn + 1], g_curD1[Nn];
__device__ int g_off2[C1n + 1], g_cur2[C1n], g_offD2[C1n + 1], g_curD2[C1n];
__device__ int g_csr1[Ee], g_q1[Ee];
__device__ int g_q2[E2n], g_d2[E2n];
__device__ __align__(16) float g_buf1[(size_t)Ee * 32];
__device__ __align__(16) float g_buf2[(size_t)E2n * 64];   // ull pairs {m0,m1}
__device__ __align__(16) float g_G2[(size_t)C1n * 1600];   // pairs (c,c+32) at 2c,2c+1
__device__ __align__(16) float g_bb2[C1n * 64];

__device__ __forceinline__ void atomicMaxFloat(float* addr, float val) {
    if (val >= 0.f) atomicMax((int*)addr, __float_as_int(val));
    else            atomicMin((unsigned int*)addr, __float_as_uint(val));
}
__device__ __forceinline__ float elu1(float v) { return v > 0.f ? v : expm1f(v); }
__device__ __forceinline__ float fixneg(float v) { return (v > -3e38f) ? v : 0.f; } // NaN/sentinel -> 0

__device__ __forceinline__ ull fma2(ull a, ull b, ull c) {
    ull d;
    asm("fma.rn.f32x2 %0, %1, %2, %3;" : "=l"(d) : "l"(a), "l"(b), "l"(c));
    return d;
}
__device__ __forceinline__ ull pack2f(float a, float b) {
    ull r;
    asm("mov.b64 %0, {%1, %2};" : "=l"(r) : "f"(a), "f"(b));
    return r;
}
__device__ __forceinline__ void unpack2f(float& a, float& b, ull v) {
    asm("mov.b64 {%0, %1}, %2;" : "=f"(a), "=f"(b) : "l"(v));
}

// ---------------- K1: degree histograms (1 edge / thread) ----------------------
__global__ void k_hist(const int* __restrict__ ei, const int* __restrict__ ei2,
                       const int* __restrict__ cl1) {
    int t = blockIdx.x * blockDim.x + threadIdx.x;
    if (t < Ee) {
        atomicAdd(&gz.deg1[ei[t]], 1);
        atomicAdd(&gz.degD1[ei[Ee + t]], 1);
    }
    if (t < E2n) {
        atomicAdd(&gz.deg2[ei2[t]], 1);
        atomicAdd(&gz.degD2[ei2[E2n + t]], 1);
    }
    if (t < Nn) atomicAdd(&gz.cntc1[cl1[t]], 1);
}

// ---------------- K2: exclusive scans (4 arrays, 1 block each) -----------------
__global__ void k_scan() {
    const int* deg; int* off; int* cur; int n;
    switch (blockIdx.x) {
        case 0:  deg = gz.deg1;  off = g_off1;  cur = g_cur1;  n = Nn;  break;
        case 1:  deg = gz.degD1; off = g_offD1; cur = g_curD1; n = Nn;  break;
        case 2:  deg = gz.deg2;  off = g_off2;  cur = g_cur2;  n = C1n; break;
        default: deg = gz.degD2; off = g_offD2; cur = g_curD2; n = C1n; break;
    }
    __shared__ int wsum[32];
    __shared__ int carry;
    int tid = threadIdx.x, lane = tid & 31, wid = tid >> 5;
    if (tid == 0) carry = 0;
    __syncthreads();
    for (int base = 0; base < n; base += 1024) {
        int idx = base + tid;
        int v = (idx < n) ? deg[idx] : 0;
        int incl = v;
#pragma unroll
        for (int o = 1; o < 32; o <<= 1) {
            int tt = __shfl_up_sync(0xffffffffu, incl, o);
            if (lane >= o) incl += tt;
        }
        if (lane == 31) wsum[wid] = incl;
        __syncthreads();
        if (wid == 0) {
            int s = wsum[lane];
#pragma unroll
            for (int o = 1; o < 32; o <<= 1) {
                int tt = __shfl_up_sync(0xffffffffu, s, o);
                if (lane >= o) s += tt;
            }
            wsum[lane] = s;
        }
        __syncthreads();
        int woff = (wid == 0) ? 0 : wsum[wid - 1];
        int c0 = carry;
        if (idx < n) { int ex = c0 + woff + incl - v; off[idx] = ex; cur[idx] = ex; }
        __syncthreads();
        if (tid == 0) carry = c0 + wsum[31];
        __syncthreads();
    }
    if (threadIdx.x == 0) off[n] = carry;
}

// ---------------- K3: scatter edge ids + dst slots + dst ids -------------------
__global__ void k_scat(const int* __restrict__ ei, const int* __restrict__ ei2) {
    int t = blockIdx.x * blockDim.x + threadIdx.x;
    if (t < Ee) {
        int q = atomicAdd(&g_curD1[ei[Ee + t]], 1);
        int p = atomicAdd(&g_cur1[ei[t]], 1);
        g_csr1[p] = t;
        g_q1[p] = q;
    }
    if (t < E2n) {
        int dst = ei2[E2n + t];
        int q = atomicAdd(&g_curD2[dst], 1);
        int p = atomicAdd(&g_cur2[ei2[t]], 1);
        g_q2[p] = q;
        g_d2[p] = dst;
    }
}

// ---------------- K4: conv1 by src (one warp per node, 4-way acc ILP) ----------
__global__ void __launch_bounds__(256) k_conv1(
        const float* __restrict__ x, const float* __restrict__ ea,
        const float* __restrict__ w1a, const float* __restrict__ b1a,
        const float* __restrict__ w1b, const float* __restrict__ b1b) {
    __shared__ __align__(16) float w1s[4800 + 192];
    int tid = threadIdx.x;
    for (int j = tid; j < 1248; j += 256) {
        float4 val;
        if (j < 1200) val = ((const float4*)w1b)[j];
        else          val = ((const float4*)b1b)[j - 1200];
        ((float4*)w1s)[j] = val;
    }
    __syncthreads();
    int v = (blockIdx.x * blockDim.x + tid) >> 5;
    int lane = tid & 31;
    if (v >= Nn) return;
    float xv[6];
#pragma unroll
    for (int i = 0; i < 6; i++) xv[i] = x[v * 6 + i];
    float G[25];
#pragma unroll
    for (int r = 0; r < 25; r++) {
        float a = 0.f;
#pragma unroll
        for (int i = 0; i < 6; i++) a = fmaf(xv[i], w1s[r * 192 + i * 32 + lane], a);
        G[r] = a;
    }
    float bb = 0.f;
#pragma unroll
    for (int i = 0; i < 6; i++) bb = fmaf(xv[i], w1s[4800 + i * 32 + lane], bb);
    float wa0 = 0.f, wa1 = 0.f, wa2 = 0.f, ba = 0.f;
    if (lane < 25) { wa0 = w1a[lane]; wa1 = w1a[25 + lane]; wa2 = w1a[50 + lane]; ba = b1a[lane]; }
    int p0 = g_off1[v], p1 = g_off1[v + 1];
    for (int p = p0; p < p1; p++) {
        int e = g_csr1[p];
        int pd = g_q1[p];
        float a0 = ea[3 * e], a1 = ea[3 * e + 1], a2 = ea[3 * e + 2];
        float h = fmaxf(fmaf(a0, wa0, fmaf(a1, wa1, fmaf(a2, wa2, ba))), 0.f);
        // 4 independent accumulator chains (FFMA lat 4: chain 100 -> ~28 cyc)
        float m0 = bb, m1 = 0.f, m2 = 0.f, m3 = 0.f;
#pragma unroll
        for (int r = 0; r < 24; r += 4) {
            m0 = fmaf(__shfl_sync(0xffffffffu, h, r),     G[r],     m0);
            m1 = fmaf(__shfl_sync(0xffffffffu, h, r + 1), G[r + 1], m1);
            m2 = fmaf(__shfl_sync(0xffffffffu, h, r + 2), G[r + 2], m2);
            m3 = fmaf(__shfl_sync(0xffffffffu, h, r + 3), G[r + 3], m3);
        }
        m0 = fmaf(__shfl_sync(0xffffffffu, h, 24), G[24], m0);
        g_buf1[(size_t)pd * 32 + lane] = (m0 + m1) + (m2 + m3);
    }
}

// ---------------- K5: node1 = segment-mean(buf1) + root + elu + pool1 ----------
__global__ void k_node1(const float* __restrict__ x, const float* __restrict__ pos,
                        const int* __restrict__ batch, const int* __restrict__ cl1,
                        const float* __restrict__ root1, const float* __restrict__ bias1) {
    int n = (blockIdx.x * blockDim.x + threadIdx.x) >> 5;
    int lane = threadIdx.x & 31;
    if (n >= Nn) return;
    int p0 = g_offD1[n], p1 = g_offD1[n + 1];
    float acc = 0.f, acc2 = 0.f;
    int p = p0;
    for (; p + 1 < p1; p += 2) {
        acc  += g_buf1[(size_t)p * 32 + lane];
        acc2 += g_buf1[(size_t)(p + 1) * 32 + lane];
    }
    if (p < p1) acc += g_buf1[(size_t)p * 32 + lane];
    acc += acc2;
    float v = acc / fmaxf((float)(p1 - p0), 1.f) + bias1[lane];
#pragma unroll
    for (int i = 0; i < 6; i++) v = fmaf(x[n * 6 + i], root1[i * 32 + lane], v);
    float x1 = elu1(v);
    int c = cl1[n];
    atomicMaxFloat(&gf.xp[c * 32 + lane], x1);
    if (lane < 3) atomicAdd(&gz.possum[c * 3 + lane], pos[n * 3 + lane]);
    if (lane == 0) atomicMax(&gf.batchp[c], batch[n]);
}

// ---------------- K6: global max |cart| (posp divided inline) ------------------
__global__ void k_maxabs(const int* __restrict__ ei2) {
    int e = blockIdx.x * blockDim.x + threadIdx.x;
    float m = 0.f;
    if (e < E2n) {
        int s = ei2[e], d = ei2[E2n + e];
        float is = 1.f / fmaxf((float)gz.cntc1[s], 1.f);
        float id = 1.f / fmaxf((float)gz.cntc1[d], 1.f);
#pragma unroll
        for (int k = 0; k < 3; k++)
            m = fmaxf(m, fabsf(gz.possum[s * 3 + k] * is - gz.possum[d * 3 + k] * id));
    }
#pragma unroll
    for (int o = 16; o; o >>= 1) m = fmaxf(m, __shfl_xor_sync(0xffffffffu, m, o));
    if ((threadIdx.x & 31) == 0) atomicMax((int*)&gz.maxabs, __float_as_int(m));
}

// ---------------- K7: G2 = xp @ w2b via packed f32x2 FMA -----------------------
__global__ void __launch_bounds__(256) k_G2(const float* __restrict__ w2b,
                                            const float* __restrict__ b2b) {
    __shared__ __align__(16) float wsp[2048];       // [i][c][2] pairs {w[c], w[c+32]}
    __shared__ __align__(16) float2 xdup[128 * 33]; // [vv][i] duplicated {x,x}
    int tid = threadIdx.x;
    int vbase = blockIdx.x * 128;
    int rs = blockIdx.y;
    const float* wsrc = (rs < 25) ? (w2b + rs * 2048) : b2b;
    for (int j = tid; j < 2048; j += 256) {
        int i = j >> 6, col = j & 63;
        int c = col & 31, s = col >> 5;
        wsp[i * 64 + c * 2 + s] = wsrc[j];
    }
    for (int idx = tid; idx < 4096; idx += 256) {
        int vv = idx >> 5, i = idx & 31;
        float val = (vbase + vv < C1n) ? fixneg(gf.xp[(vbase + vv) * 32 + i]) : 0.f;
        xdup[vv * 33 + i] = make_float2(val, val);
    }
    __syncthreads();
    int colg = tid & 7, nodeg = tid >> 3;
    int c4 = colg * 4;
    int n4 = nodeg * 4;
    ull acc[4][4];
#pragma unroll
    for (int n = 0; n < 4; n++)
#pragma unroll
        for (int p = 0; p < 4; p++) acc[n][p] = 0ULL;
#pragma unroll 8
    for (int i = 0; i < 32; i++) {
        ulonglong2 wA = *(const ulonglong2*)&wsp[i * 64 + c4 * 2];
        ulonglong2 wB = *(const ulonglong2*)&wsp[i * 64 + c4 * 2 + 4];
        ull xp_[4];
#pragma unroll
        for (int n = 0; n < 4; n++)
            xp_[n] = *(const ull*)&xdup[(n4 + n) * 33 + i];
#pragma unroll
        for (int n = 0; n < 4; n++) {
            acc[n][0] = fma2(wA.x, xp_[n], acc[n][0]);
            acc[n][1] = fma2(wA.y, xp_[n], acc[n][1]);
            acc[n][2] = fma2(wB.x, xp_[n], acc[n][2]);
            acc[n][3] = fma2(wB.y, xp_[n], acc[n][3]);
        }
    }
#pragma unroll
    for (int n = 0; n < 4; n++) {
        int v = vbase + n4 + n;
        if (v < C1n) {
            float* dst = (rs < 25) ? (g_G2 + (size_t)v * 1600 + rs * 64 + c4 * 2)
                                   : (g_bb2 + v * 64 + c4 * 2);
            ulonglong2 o0; o0.x = acc[n][0]; o0.y = acc[n][1];
            ulonglong2 o1; o1.x = acc[n][2]; o1.y = acc[n][3];
            *(ulonglong2*)dst = o0;
            *(ulonglong2*)(dst + 4) = o1;
        }
    }
}

// ---------------- K8: conv2 by src (warp per C1 node, 2x2 acc ILP) -------------
__global__ void k_conv2(const float* __restrict__ w2a, const float* __restrict__ b2a) {
    int v = (blockIdx.x * blockDim.x + threadIdx.x) >> 5;
    int lane = threadIdx.x & 31;
    if (v >= C1n) return;
    const ull* Gp = (const ull*)(g_G2 + (size_t)v * 1600);
    float G0[25], G1[25];
#pragma unroll
    for (int r = 0; r < 25; r++) {
        ull g = Gp[r * 32 + lane];
        unpack2f(G0[r], G1[r], g);
    }
    float bb0, bb1;
    {
        ull b = ((const ull*)g_bb2)[v * 32 + lane];
        unpack2f(bb0, bb1, b);
    }
    float invS = 1.f / fmaxf((float)gz.cntc1[v], 1.f);
    float pv0 = gz.possum[v * 3] * invS, pv1 = gz.possum[v * 3 + 1] * invS,
          pv2 = gz.possum[v * 3 + 2] * invS;
    float inv = 0.5f / gz.maxabs;
    float wa0 = 0.f, wa1 = 0.f, wa2 = 0.f, ba = 0.f;
    if (lane < 25) { wa0 = w2a[lane]; wa1 = w2a[25 + lane]; wa2 = w2a[50 + lane]; ba = b2a[lane]; }
    int p0 = g_off2[v], p1 = g_off2[v + 1];
    for (int p = p0; p < p1; p++) {
        int pd = g_q2[p];
        int dst = g_d2[p];
        float invD = 1.f / fmaxf((float)gz.cntc1[dst], 1.f);
        float e0 = fmaf(pv0 - gz.possum[dst * 3] * invD,     inv, 0.5f);
        float e1 = fmaf(pv1 - gz.possum[dst * 3 + 1] * invD, inv, 0.5f);
        float e2 = fmaf(pv2 - gz.possum[dst * 3 + 2] * invD, inv, 0.5f);
        float h = fmaxf(fmaf(e0, wa0, fmaf(e1, wa1, fmaf(e2, wa2, ba))), 0.f);
        // 2 chains per output column (4 total)
        float m0a = bb0, m0b = 0.f, m1a = bb1, m1b = 0.f;
#pragma unroll
        for (int r = 0; r < 24; r += 2) {
            float ha = __shfl_sync(0xffffffffu, h, r);
            float hb = __shfl_sync(0xffffffffu, h, r + 1);
            m0a = fmaf(ha, G0[r], m0a);
            m1a = fmaf(ha, G1[r], m1a);
            m0b = fmaf(hb, G0[r + 1], m0b);
            m1b = fmaf(hb, G1[r + 1], m1b);
        }
        {
            float ha = __shfl_sync(0xffffffffu, h, 24);
            m0a = fmaf(ha, G0[24], m0a);
            m1a = fmaf(ha, G1[24], m1a);
        }
        ((ull*)g_buf2)[(size_t)pd * 32 + lane] = pack2f(m0a + m0b, m1a + m1b);
    }
}

// ---------------- K9: node2 + pool2 scatter -------------------------------------
__global__ void k_node2(const int* __restrict__ cl2, const float* __restrict__ root2,
                        const float* __restrict__ bias2) {
    int c = (blockIdx.x * blockDim.x + threadIdx.x) >> 5;
    int lane = threadIdx.x & 31;
    if (c >= C1n) return;
    int p0 = g_offD2[c], p1 = g_offD2[c + 1];
    const ull ONE2 = pack2f(1.f, 1.f);
    ull accp = 0ULL, accq = 0ULL;
    int p = p0;
    for (; p + 1 < p1; p += 2) {
        accp = fma2(((const ull*)g_buf2)[(size_t)p * 32 + lane], ONE2, accp);
        accq = fma2(((const ull*)g_buf2)[(size_t)(p + 1) * 32 + lane], ONE2, accq);
    }
    if (p < p1) accp = fma2(((const ull*)g_buf2)[(size_t)p * 32 + lane], ONE2, accp);
    accp = fma2(accq, ONE2, accp);
    float a0, a1; unpack2f(a0, a1, accp);
    float cnt = fmaxf((float)(p1 - p0), 1.f);
    float v0a = a0 / cnt + bias2[lane], v0b = 0.f;
    float v1a = a1 / cnt + bias2[lane + 32], v1b = 0.f;
    float xpi = fixneg(gf.xp[c * 32 + lane]);
#pragma unroll
    for (int i = 0; i < 32; i += 2) {
        float xa = __shfl_sync(0xffffffffu, xpi, i);
        float xb = __shfl_sync(0xffffffffu, xpi, i + 1);
        v0a = fmaf(xa, root2[i * 64 + lane], v0a);
        v1a = fmaf(xa, root2[i * 64 + lane + 32], v1a);
        v0b = fmaf(xb, root2[(i + 1) * 64 + lane], v0b);
        v1b = fmaf(xb, root2[(i + 1) * 64 + lane + 32], v1b);
    }
    float e0 = elu1(v0a + v0b), e1 = elu1(v1a + v1b);
    int c2 = cl2[c];
    atomicMaxFloat(&gf.x3[c2 * 64 + lane], e0);
    atomicMaxFloat(&gf.x3[c2 * 64 + lane + 32], e1);
    if (lane == 0) atomicMax(&gf.batch2[c2], max(gf.batchp[c], 0));
}

// ---------------- K10: pool2 finalize + global mean scatter ---------------------
__global__ void k_pool2() {
    int c = (blockIdx.x * blockDim.x + threadIdx.x) >> 5;
    int lane = threadIdx.x & 31;
    if (c >= C2n) return;
    float v0 = fixneg(gf.x3[c * 64 + lane]);
    float v1 = fixneg(gf.x3[c * 64 + lane + 32]);
    int b = max(gf.batch2[c], 0);
    atomicAdd(&gz.gsum[b * 64 + lane], v0);
    atomicAdd(&gz.gsum[b * 64 + lane + 32], v1);
    if (lane == 0) atomicAdd(&gz.gcnt[b], 1.f);
}

// ---------------- K11: FC head + log_softmax ------------------------------------
__global__ void k_head(const float* __restrict__ fc1w, const float* __restrict__ fc1b,
                       const float* __restrict__ fc2w, const float* __restrict__ fc2b,
                       float* __restrict__ out) {
    __shared__ float g[16 * 64];
    __shared__ float hh[16 * 128];
    __shared__ float lg[16 * 10];
    int tid = threadIdx.x;
    for (int i = tid; i < 16 * 64; i += 256) g[i] = gz.gsum[i] / fmaxf(gz.gcnt[i >> 6], 1.f);
    __syncthreads();
    for (int o = tid; o < 16 * 128; o += 256) {
        int b = o >> 7, j = o & 127;
        float acc = fc1b[j];
        for (int k = 0; k < 64; k++) acc = fmaf(g[b * 64 + k], fc1w[k * 128 + j], acc);
        hh[o] = elu1(acc);
    }
    __syncthreads();
    if (tid < 160) {
        int b = tid / 10, k = tid % 10;
        float acc = fc2b[k];
        for (int j = 0; j < 128; j++) acc = fmaf(hh[b * 128 + j], fc2w[j * 10 + k], acc);
        lg[tid] = acc;
    }
    __syncthreads();
    if (tid < 16) {
        float m = -1e30f;
        for (int k = 0; k < 10; k++) m = fmaxf(m, lg[tid * 10 + k]);
        float s = 0.f;
        for (int k = 0; k < 10; k++) s += expf(lg[tid * 10 + k] - m);
        float ls = logf(s) + m;
        for (int k = 0; k < 10; k++) out[tid * 10 + k] = lg[tid * 10 + k] - ls;
    }
}

// ---------------- host launcher --------------------------------------------------
extern "C" void kernel_launch(void* const* d_in, const int* in_sizes, int n_in,
                              void* d_out, int out_size) {
    const float *x, *ea, *pos, *w1a, *b1a, *w1b, *b1b, *root1, *bias1;
    const float *w2a, *b2a, *w2b, *b2b, *root2, *bias2, *fc1w, *fc1b, *fc2w, *fc2b;
    const int *ei, *batch, *cl1, *ei2, *cl2;

    if (in_sizes[3] == 2 * Ee) {
        x = (const float*)d_in[0];  ea = (const float*)d_in[1];  pos = (const float*)d_in[2];
        ei = (const int*)d_in[3];   batch = (const int*)d_in[4]; cl1 = (const int*)d_in[5];
        ei2 = (const int*)d_in[6];  cl2 = (const int*)d_in[7];
        w1a = (const float*)d_in[8];  b1a = (const float*)d_in[9];
        w1b = (const float*)d_in[10]; b1b = (const float*)d_in[11];
        root1 = (const float*)d_in[12]; bias1 = (const float*)d_in[13];
        w2a = (const float*)d_in[14]; b2a = (const float*)d_in[15];
        w2b = (const float*)d_in[16]; b2b = (const float*)d_in[17];
        root2 = (const float*)d_in[18]; bias2 = (const float*)d_in[19];
        fc1w = (const float*)d_in[20]; fc1b = (const float*)d_in[21];
        fc2w = (const float*)d_in[22]; fc2b = (const float*)d_in[23];
    } else {
        x = (const float*)d_in[0];  ea = (const float*)d_in[1];  pos = (const float*)d_in[2];
        w1a = (const float*)d_in[3];  b1a = (const float*)d_in[4];
        w1b = (const float*)d_in[5];  b1b = (const float*)d_in[6];
        root1 = (const float*)d_in[7]; bias1 = (const float*)d_in[8];
        w2a = (const float*)d_in[9];  b2a = (const float*)d_in[10];
        w2b = (const float*)d_in[11]; b2b = (const float*)d_in[12];
        root2 = (const float*)d_in[13]; bias2 = (const float*)d_in[14];
        fc1w = (const float*)d_in[15]; fc1b = (const float*)d_in[16];
        fc2w = (const float*)d_in[17]; fc2b = (const float*)d_in[18];
        ei = (const int*)d_in[19];  batch = (const int*)d_in[20]; cl1 = (const int*)d_in[21];
        ei2 = (const int*)d_in[22]; cl2 = (const int*)d_in[23];
    }

    void *pz = nullptr, *pf = nullptr;
    cudaGetSymbolAddress(&pz, gz);
    cudaGetSymbolAddress(&pf, gf);
    cudaMemsetAsync(pz, 0, sizeof(ZBlk));
    cudaMemsetAsync(pf, 0xff, sizeof(FBlk));

    k_hist<<<(Ee + 255) / 256, 256>>>(ei, ei2, cl1);
    k_scan<<<4, 1024>>>();
    k_scat<<<(Ee + 255) / 256, 256>>>(ei, ei2);
    k_conv1<<<3750, 256>>>(x, ea, w1a, b1a, w1b, b1b);
    k_node1<<<3750, 256>>>(x, pos, batch, cl1, root1, bias1);
    k_maxabs<<<(E2n + 255) / 256, 256>>>(ei2);
    k_G2<<<dim3(118, 26), 256>>>(w2b, b2b);
    k_conv2<<<1875, 256>>>(w2a, b2a);
    k_node2<<<1875, 256>>>(cl2, root2, bias2);
    k_pool2<<<938, 256>>>();
    k_head<<<1, 256>>>(fc1w, fc1b, fc2w, fc2b, (float*)d_out);
}

// round 8
// speedup vs baseline: 1.1980x; 1.1014x over previous
#include <cuda_runtime.h>
#include <math.h>
#include <limits.h>

#define Nn 30000
#define Ee 400000
#define C1n 15000
#define E2n 100000
#define C2n 7500
#define Bn 16

#define T1S 168   // T1 row stride (162 used)
#define K1 162    // 150 w1b + 6 b1b + 6 root1
#define T2S 864   // T2 row stride (864 used exactly)
#define K2 864    // 800 w2b + 32 b2b + 32 root2

typedef unsigned long long ull;

// ---------------- zero-init block (single memset 0) ---------------------------
struct ZBlk {
    int   degD1[Nn];
    int   degD2[C1n], cntc1[C1n];
    float possum[C1n * 3];
    float gsum[Bn * 64];
    float gcnt[Bn];
    float maxabs;
};
// ---------------- 0xff-init block (single memset 0xff) ------------------------
struct FBlk {
    float xp[C1n * 32];      // 0xffffffff sentinel (loses to all atomicMaxFloat)
    float x3[C2n * 64];
    int   batchp[C1n];       // -1
    int   batch2[C2n];       // -1
};
__device__ ZBlk gz;
__device__ FBlk gf;

// ---------------- uninitialized scratch ----------------------------------------
__device__ int g_offD1[Nn + 1], g_curD1[Nn];
__device__ int g_offD2[C1n + 1], g_curD2[C1n];
__device__ __align__(16) float4 g_e4[Ee];          // {ea0,ea1,ea2, src-bits} dst-sorted
__device__ int g_csrD2s[E2n];                      // src ids dst-sorted
__device__ __align__(16) float g_T1[(size_t)Nn * T1S];
__device__ __align__(16) float g_T2[(size_t)C1n * T2S];

__device__ __forceinline__ void atomicMaxFloat(float* addr, float val) {
    if (val >= 0.f) atomicMax((int*)addr, __float_as_int(val));
    else            atomicMin((unsigned int*)addr, __float_as_uint(val));
}
__device__ __forceinline__ float elu1(float v) { return v > 0.f ? v : expm1f(v); }
__device__ __forceinline__ float fixneg(float v) { return (v > -3e38f) ? v : 0.f; }

// ---------------- K1: degree histograms ----------------------------------------
__global__ void k_hist(const int* __restrict__ ei, const int* __restrict__ ei2,
                       const int* __restrict__ cl1) {
    int t = blockIdx.x * blockDim.x + threadIdx.x;
    if (t < Ee)  atomicAdd(&gz.degD1[ei[Ee + t]], 1);
    if (t < E2n) atomicAdd(&gz.degD2[ei2[E2n + t]], 1);
    if (t < Nn)  atomicAdd(&gz.cntc1[cl1[t]], 1);
}

// ---------------- K2: exclusive scans (2 arrays, 1 block each) ------------------
__global__ void k_scan() {
    const int* deg; int* off; int* cur; int n;
    if (blockIdx.x == 0) { deg = gz.degD1; off = g_offD1; cur = g_curD1; n = Nn; }
    else                 { deg = gz.degD2; off = g_offD2; cur = g_curD2; n = C1n; }
    __shared__ int wsum[32];
    __shared__ int carry;
    int tid = threadIdx.x, lane = tid & 31, wid = tid >> 5;
    if (tid == 0) carry = 0;
    __syncthreads();
    for (int base = 0; base < n; base += 1024) {
        int idx = base + tid;
        int v = (idx < n) ? deg[idx] : 0;
        int incl = v;
#pragma unroll
        for (int o = 1; o < 32; o <<= 1) {
            int tt = __shfl_up_sync(0xffffffffu, incl, o);
            if (lane >= o) incl += tt;
        }
        if (lane == 31) wsum[wid] = incl;
        __syncthreads();
        if (wid == 0) {
            int s = wsum[lane];
#pragma unroll
            for (int o = 1; o < 32; o <<= 1) {
                int tt = __shfl_up_sync(0xffffffffu, s, o);
                if (lane >= o) s += tt;
            }
            wsum[lane] = s;
        }
        __syncthreads();
        int woff = (wid == 0) ? 0 : wsum[wid - 1];
        int c0 = carry;
        if (idx < n) { int ex = c0 + woff + incl - v; off[idx] = ex; cur[idx] = ex; }
        __syncthreads();
        if (tid == 0) carry = c0 + wsum[31];
        __syncthreads();
    }
    if (threadIdx.x == 0) off[n] = carry;
}

// ---------------- K3: scatter (dst-sorted edge payloads) ------------------------
__global__ void k_scat(const int* __restrict__ ei, const int* __restrict__ ei2,
                       const float* __restrict__ ea) {
    int t = blockIdx.x * blockDim.x + threadIdx.x;
    if (t < Ee) {
        int p = atomicAdd(&g_curD1[ei[Ee + t]], 1);
        float4 v;
        v.x = ea[3 * t]; v.y = ea[3 * t + 1]; v.z = ea[3 * t + 2];
        v.w = __int_as_float(ei[t]);
        g_e4[p] = v;
    }
    if (t < E2n) {
        int p = atomicAdd(&g_curD2[ei2[E2n + t]], 1);
        g_csrD2s[p] = ei2[t];
    }
}

// ---------------- K4: conv1 edge pass -> T1 (warp per dst node) -----------------
// lane r<25: T[r][i] += h_r * x_i ; lane 25: h==1 (xsum row) ; lane 26: root row.
__global__ void __launch_bounds__(256) k_conv1(
        const float* __restrict__ x, const float* __restrict__ pos,
        const int* __restrict__ batch, const int* __restrict__ cl1,
        const float* __restrict__ w1a, const float* __restrict__ b1a) {
    int tid = threadIdx.x;
    int d = (blockIdx.x * blockDim.x + tid) >> 5;
    int lane = tid & 31;
    if (d >= Nn) return;
    float wa0 = 0.f, wa1 = 0.f, wa2 = 0.f, ba = 0.f;
    if (lane < 25) { wa0 = w1a[lane]; wa1 = w1a[25 + lane]; wa2 = w1a[50 + lane]; ba = b1a[lane]; }
    else if (lane == 25) ba = 1.f;   // h == 1 -> accumulates x-sum (bias row)
    float acc0 = 0.f, acc1 = 0.f, acc2 = 0.f, acc3 = 0.f, acc4 = 0.f, acc5 = 0.f;
    int p0 = g_offD1[d], p1 = g_offD1[d + 1];
    for (int p = p0; p < p1; p++) {
        float4 e4 = g_e4[p];
        int src = __float_as_int(e4.w);
        const float2* xs = (const float2*)(x + src * 6);
        float2 x01 = xs[0], x23 = xs[1], x45 = xs[2];
        float h = fmaxf(fmaf(e4.x, wa0, fmaf(e4.y, wa1, fmaf(e4.z, wa2, ba))), 0.f);
        acc0 = fmaf(h, x01.x, acc0); acc1 = fmaf(h, x01.y, acc1);
        acc2 = fmaf(h, x23.x, acc2); acc3 = fmaf(h, x23.y, acc3);
        acc4 = fmaf(h, x45.x, acc4); acc5 = fmaf(h, x45.y, acc5);
    }
    float invd = 1.f / fmaxf((float)(p1 - p0), 1.f);
    float* Trow = g_T1 + (size_t)d * T1S + lane * 6;
    if (lane < 26) {
        Trow[0] = acc0 * invd; Trow[1] = acc1 * invd; Trow[2] = acc2 * invd;
        Trow[3] = acc3 * invd; Trow[4] = acc4 * invd; Trow[5] = acc5 * invd;
    } else if (lane == 26) {
        // root columns: raw x[d] (not divided)
#pragma unroll
        for (int i = 0; i < 6; i++) Trow[i] = x[d * 6 + i];
    } else if (lane == 27) {
        atomicMax(&gf.batchp[cl1[d]], batch[d]);
    } else if (lane >= 29) {
        atomicAdd(&gz.possum[cl1[d] * 3 + (lane - 29)], pos[d * 3 + (lane - 29)]);
    }
}

// ---------------- K5: gemm1  out = T1 @ [w1b|b1b|root1] + bias1 -> elu -> pool1 --
__global__ void __launch_bounds__(256) k_gemm1(
        const float* __restrict__ w1b, const float* __restrict__ b1b,
        const float* __restrict__ root1, const float* __restrict__ bias1,
        const int* __restrict__ cl1) {
    __shared__ __align__(16) float Ws[192 * 32];      // zero-padded K rows
    __shared__ __align__(16) float Ts[32 * 136];      // [k][n], stride 136
    int tid = threadIdx.x;
    int nb = blockIdx.x * 128;
    for (int idx = tid; idx < 192 * 32; idx += 256) {
        float v = 0.f;
        if (idx < 4800)      v = w1b[idx];
        else if (idx < 4992) v = b1b[idx - 4800];
        else if (idx < 5184) v = root1[idx - 4992];
        Ws[idx] = v;
    }
    int cg = tid & 7, ng = tid >> 3;
    int c4 = cg * 4, n4 = ng * 4;
    float acc[4][4];
#pragma unroll
    for (int a = 0; a < 4; a++)
#pragma unroll
        for (int b = 0; b < 4; b++) acc[a][b] = 0.f;
    for (int kk = 0; kk < K1; kk += 32) {
        __syncthreads();
        for (int idx = tid; idx < 128 * 32; idx += 256) {
            int n = idx >> 5, k = idx & 31;
            float v = 0.f;
            if (kk + k < K1 && nb + n < Nn) v = g_T1[(size_t)(nb + n) * T1S + kk + k];
            Ts[k * 136 + n] = v;
        }
        __syncthreads();
#pragma unroll 8
        for (int k = 0; k < 32; k++) {
            float4 tv = *(const float4*)&Ts[k * 136 + n4];
            float4 wv = *(const float4*)&Ws[(kk + k) * 32 + c4];
            float ta[4] = {tv.x, tv.y, tv.z, tv.w};
            float wa[4] = {wv.x, wv.y, wv.z, wv.w};
#pragma unroll
            for (int a = 0; a < 4; a++)
#pragma unroll
                for (int b = 0; b < 4; b++) acc[a][b] = fmaf(ta[a], wa[b], acc[a][b]);
        }
    }
#pragma unroll
    for (int a = 0; a < 4; a++) {
        int n = nb + n4 + a;
        if (n >= Nn) continue;
        int c = cl1[n];
#pragma unroll
        for (int b = 0; b < 4; b++) {
            float v = elu1(acc[a][b] + bias1[c4 + b]);
            atomicMaxFloat(&gf.xp[c * 32 + c4 + b], v);
        }
    }
}

// ---------------- K6: global max |cart| ----------------------------------------
__global__ void k_maxabs(const int* __restrict__ ei2) {
    int e = blockIdx.x * blockDim.x + threadIdx.x;
    float m = 0.f;
    if (e < E2n) {
        int s = ei2[e], d = ei2[E2n + e];
        float is = 1.f / fmaxf((float)gz.cntc1[s], 1.f);
        float id = 1.f / fmaxf((float)gz.cntc1[d], 1.f);
#pragma unroll
        for (int k = 0; k < 3; k++)
            m = fmaxf(m, fabsf(gz.possum[s * 3 + k] * is - gz.possum[d * 3 + k] * id));
    }
#pragma unroll
    for (int o = 16; o; o >>= 1) m = fmaxf(m, __shfl_xor_sync(0xffffffffu, m, o));
    if ((threadIdx.x & 31) == 0) atomicMax((int*)&gz.maxabs, __float_as_int(m));
}

// ---------------- K7: conv2 edge pass -> T2 (warp per dst C1 node) ---------------
// lane i owns xp column i; acc[r] (r=0..24 real h rows, r=25 h==1 xpsum row).
__global__ void __launch_bounds__(256) k_conv2(
        const float* __restrict__ w2a, const float* __restrict__ b2a) {
    int tid = threadIdx.x;
    int d = (blockIdx.x * blockDim.x + tid) >> 5;
    int lane = tid & 31;
    if (d >= C1n) return;
    float wa0 = 0.f, wa1 = 0.f, wa2 = 0.f, ba = 0.f;
    if (lane < 25) { wa0 = w2a[lane]; wa1 = w2a[25 + lane]; wa2 = w2a[50 + lane]; ba = b2a[lane]; }
    else if (lane == 25) ba = 1.f;
    float invcd = 1.f / fmaxf((float)gz.cntc1[d], 1.f);
    float pd0 = gz.possum[d * 3] * invcd, pd1 = gz.possum[d * 3 + 1] * invcd,
          pd2 = gz.possum[d * 3 + 2] * invcd;
    float inv = 0.5f / gz.maxabs;
    float acc[26];
#pragma unroll
    for (int r = 0; r < 26; r++) acc[r] = 0.f;
    int p0 = g_offD2[d], p1 = g_offD2[d + 1];
    for (int p = p0; p < p1; p++) {
        int src = g_csrD2s[p];
        float invcs = 1.f / fmaxf((float)gz.cntc1[src], 1.f);
        float e0 = fmaf(gz.possum[src * 3] * invcs - pd0,     inv, 0.5f);
        float e1 = fmaf(gz.possum[src * 3 + 1] * invcs - pd1, inv, 0.5f);
        float e2 = fmaf(gz.possum[src * 3 + 2] * invcs - pd2, inv, 0.5f);
        float h = fmaxf(fmaf(e0, wa0, fmaf(e1, wa1, fmaf(e2, wa2, ba))), 0.f);
        float xpi = fixneg(gf.xp[src * 32 + lane]);
#pragma unroll
        for (int r = 0; r < 26; r++) {
            float hr = __shfl_sync(0xffffffffu, h, r);
            acc[r] = fmaf(hr, xpi, acc[r]);
        }
    }
    float invd = 1.f / fmaxf((float)(p1 - p0), 1.f);
    float* Trow = g_T2 + (size_t)d * T2S;
#pragma unroll
    for (int r = 0; r < 26; r++) Trow[r * 32 + lane] = acc[r] * invd;
    Trow[832 + lane] = fixneg(gf.xp[d * 32 + lane]);   // root columns (not divided)
}

// ---------------- K8: gemm2  out = T2 @ [w2b|b2b|root2] + bias2 -> elu -> pool2 --
__global__ void __launch_bounds__(256) k_gemm2(
        const float* __restrict__ w2b, const float* __restrict__ b2b,
        const float* __restrict__ root2, const float* __restrict__ bias2,
        const int* __restrict__ cl2) {
    __shared__ __align__(16) float Ws[64 * 64];
    __shared__ __align__(16) float Ts[64 * 68];
    int tid = threadIdx.x;
    int nb = blockIdx.x * 64;
    int cg = tid & 15, ng = tid >> 4;
    int c4 = cg * 4, n4 = ng * 4;
    float acc[4][4];
#pragma unroll
    for (int a = 0; a < 4; a++)
#pragma unroll
        for (int b = 0; b < 4; b++) acc[a][b] = 0.f;
    for (int kk = 0; kk < K2; kk += 64) {
        __syncthreads();
        for (int idx = tid; idx < 64 * 64; idx += 256) {
            int kr = idx >> 6, c = idx & 63;
            int k = kk + kr;
            float v;
            if (k < 800)      v = w2b[k * 64 + c];
            else if (k < 832) v = b2b[(k - 800) * 64 + c];
            else              v = root2[(k - 832) * 64 + c];
            Ws[idx] = v;
            int n = idx >> 6, kt = idx & 63;
            float tv = 0.f;
            if (nb + n < C1n) tv = g_T2[(size_t)(nb + n) * T2S + kk + kt];
            Ts[kt * 68 + n] = tv;
        }
        __syncthreads();
#pragma unroll 8
        for (int k = 0; k < 64; k++) {
            float4 tv = *(const float4*)&Ts[k * 68 + n4];
            float4 wv = *(const float4*)&Ws[k * 64 + c4];
            float ta[4] = {tv.x, tv.y, tv.z, tv.w};
            float wa[4] = {wv.x, wv.y, wv.z, wv.w};
#pragma unroll
            for (int a = 0; a < 4; a++)
#pragma unroll
                for (int b = 0; b < 4; b++) acc[a][b] = fmaf(ta[a], wa[b], acc[a][b]);
        }
    }
#pragma unroll
    for (int a = 0; a < 4; a++) {
        int n = nb + n4 + a;
        if (n >= C1n) continue;
        int c2 = cl2[n];
#pragma unroll
        for (int b = 0; b < 4; b++) {
            float v = elu1(acc[a][b] + bias2[c4 + b]);
            atomicMaxFloat(&gf.x3[c2 * 64 + c4 + b], v);
        }
        if (cg == 0) atomicMax(&gf.batch2[c2], max(gf.batchp[n], 0));
    }
}

// ---------------- K9: pool2 finalize + global mean scatter ----------------------
__global__ void k_pool2() {
    int c = (blockIdx.x * blockDim.x + threadIdx.x) >> 5;
    int lane = threadIdx.x & 31;
    if (c >= C2n) return;
    float v0 = fixneg(gf.x3[c * 64 + lane]);
    float v1 = fixneg(gf.x3[c * 64 + lane + 32]);
    int b = max(gf.batch2[c], 0);
    atomicAdd(&gz.gsum[b * 64 + lane], v0);
    atomicAdd(&gz.gsum[b * 64 + lane + 32], v1);
    if (lane == 0) atomicAdd(&gz.gcnt[b], 1.f);
}

// ---------------- K10: FC head + log_softmax ------------------------------------
__global__ void k_head(const float* __restrict__ fc1w, const float* __restrict__ fc1b,
                       const float* __restrict__ fc2w, const float* __restrict__ fc2b,
                       float* __restrict__ out) {
    __shared__ float g[16 * 64];
    __shared__ float hh[16 * 128];
    __shared__ float lg[16 * 10];
    int tid = threadIdx.x;
    for (int i = tid; i < 16 * 64; i += 256) g[i] = gz.gsum[i] / fmaxf(gz.gcnt[i >> 6], 1.f);
    __syncthreads();
    for (int o = tid; o < 16 * 128; o += 256) {
        int b = o >> 7, j = o & 127;
        float acc = fc1b[j];
        for (int k = 0; k < 64; k++) acc = fmaf(g[b * 64 + k], fc1w[k * 128 + j], acc);
        hh[o] = elu1(acc);
    }
    __syncthreads();
    if (tid < 160) {
        int b = tid / 10, k = tid % 10;
        float acc = fc2b[k];
        for (int j = 0; j < 128; j++) acc = fmaf(hh[b * 128 + j], fc2w[j * 10 + k], acc);
        lg[tid] = acc;
    }
    __syncthreads();
    if (tid < 16) {
        float m = -1e30f;
        for (int k = 0; k < 10; k++) m = fmaxf(m, lg[tid * 10 + k]);
        float s = 0.f;
        for (int k = 0; k < 10; k++) s += expf(lg[tid * 10 + k] - m);
        float ls = logf(s) + m;
        for (int k = 0; k < 10; k++) out[tid * 10 + k] = lg[tid * 10 + k] - ls;
    }
}

// ---------------- host launcher --------------------------------------------------
extern "C" void kernel_launch(void* const* d_in, const int* in_sizes, int n_in,
                              void* d_out, int out_size) {
    const float *x, *ea, *pos, *w1a, *b1a, *w1b, *b1b, *root1, *bias1;
    const float *w2a, *b2a, *w2b, *b2b, *root2, *bias2, *fc1w, *fc1b, *fc2w, *fc2b;
    const int *ei, *batch, *cl1, *ei2, *cl2;

    if (in_sizes[3] == 2 * Ee) {
        x = (const float*)d_in[0];  ea = (const float*)d_in[1];  pos = (const float*)d_in[2];
        ei = (const int*)d_in[3];   batch = (const int*)d_in[4]; cl1 = (const int*)d_in[5];
        ei2 = (const int*)d_in[6];  cl2 = (const int*)d_in[7];
        w1a = (const float*)d_in[8];  b1a = (const float*)d_in[9];
        w1b = (const float*)d_in[10]; b1b = (const float*)d_in[11];
        root1 = (const float*)d_in[12]; bias1 = (const float*)d_in[13];
        w2a = (const float*)d_in[14]; b2a = (const float*)d_in[15];
        w2b = (const float*)d_in[16]; b2b = (const float*)d_in[17];
        root2 = (const float*)d_in[18]; bias2 = (const float*)d_in[19];
        fc1w = (const float*)d_in[20]; fc1b = (const float*)d_in[21];
        fc2w = (const float*)d_in[22]; fc2b = (const float*)d_in[23];
    } else {
        x = (const float*)d_in[0];  ea = (const float*)d_in[1];  pos = (const float*)d_in[2];
        w1a = (const float*)d_in[3];  b1a = (const float*)d_in[4];
        w1b = (const float*)d_in[5];  b1b = (const float*)d_in[6];
        root1 = (const float*)d_in[7]; bias1 = (const float*)d_in[8];
        w2a = (const float*)d_in[9];  b2a = (const float*)d_in[10];
        w2b = (const float*)d_in[11]; b2b = (const float*)d_in[12];
        root2 = (const float*)d_in[13]; bias2 = (const float*)d_in[14];
        fc1w = (const float*)d_in[15]; fc1b = (const float*)d_in[16];
        fc2w = (const float*)d_in[17]; fc2b = (const float*)d_in[18];
        ei = (const int*)d_in[19];  batch = (const int*)d_in[20]; cl1 = (const int*)d_in[21];
        ei2 = (const int*)d_in[22]; cl2 = (const int*)d_in[23];
    }

    void *pz = nullptr, *pf = nullptr;
    cudaGetSymbolAddress(&pz, gz);
    cudaGetSymbolAddress(&pf, gf);
    cudaMemsetAsync(pz, 0, sizeof(ZBlk));
    cudaMemsetAsync(pf, 0xff, sizeof(FBlk));

    k_hist<<<(Ee + 255) / 256, 256>>>(ei, ei2, cl1);
    k_scan<<<2, 1024>>>();
    k_scat<<<(Ee + 255) / 256, 256>>>(ei, ei2, ea);
    k_conv1<<<3750, 256>>>(x, pos, batch, cl1, w1a, b1a);
    k_gemm1<<<(Nn + 127) / 128, 256>>>(w1b, b1b, root1, bias1, cl1);
    k_maxabs<<<(E2n + 255) / 256, 256>>>(ei2);
    k_conv2<<<1875, 256>>>(w2a, b2a);
    k_gemm2<<<(C1n + 63) / 64, 256>>>(w2b, b2b, root2, bias2, cl2);
    k_pool2<<<938, 256>>>();
    k_head<<<1, 256>>>(fc1w, fc1b, fc2w, fc2b, (float*)d_out);
}